// round 12
// baseline (speedup 1.0000x reference)
#include <cuda_runtime.h>
#include <cuda_bf16.h>
#include <cstdint>

#define D_DIM 256
#define FLT_BIG 3.402823466e+38f
#define NCAND 8

// scratch (static device globals; no allocations)
__device__ int8_t g_cb8[1024 * 256];      // codebook s8, scale 127*1024
__device__ float  g_codenorm[1024];
__device__ int    g_cand[32768 * NCAND];
__device__ float  g_partial[8192];
__device__ int    g_ctr;

// smem layout: A tile 32KB (s8 128x256) | B ring 3x16KB
#define OFF_B   32768
#define CO_SMEM (32768 + 49152)   // 80KB -> 2 CTAs/SM

// x quant: clip +-5, scale 127/5 ; e quant: scale 127*1024
// score = cbn[k] - 2*(5/(127*127*1024)) * dot_s32
#define XSCALE 25.4f
#define DESCALE2 6.054752e-07f    // 2*5/(127*127*1024)

// ---------------------------------------------------------------------------
// PTX helpers (plain sm_103: mma.sync + ldmatrix + cp.async only)
// ---------------------------------------------------------------------------
__device__ __forceinline__ void ldsm4(uint32_t addr, uint32_t& r0, uint32_t& r1,
                                      uint32_t& r2, uint32_t& r3) {
    asm volatile("ldmatrix.sync.aligned.m8n8.x4.shared.b16 {%0,%1,%2,%3}, [%4];"
                 : "=r"(r0), "=r"(r1), "=r"(r2), "=r"(r3) : "r"(addr));
}
// int8 IMMA: m16n8k32, byte-layout-compatible with the bf16 k16 ldmatrix path
__device__ __forceinline__ void mma16832(int* c, const uint32_t* a,
                                         uint32_t b0, uint32_t b1) {
    asm volatile(
        "mma.sync.aligned.m16n8k32.row.col.s32.s8.s8.s32 "
        "{%0,%1,%2,%3}, {%4,%5,%6,%7}, {%8,%9}, {%0,%1,%2,%3};"
        : "+r"(c[0]), "+r"(c[1]), "+r"(c[2]), "+r"(c[3])
        : "r"(a[0]), "r"(a[1]), "r"(a[2]), "r"(a[3]), "r"(b0), "r"(b1));
}
__device__ __forceinline__ void cpasync16(uint32_t dst, const void* src) {
    asm volatile("cp.async.cg.shared.global [%0], [%1], 16;" :: "r"(dst), "l"(src));
}
__device__ __forceinline__ void cpcommit() { asm volatile("cp.async.commit_group;"); }
__device__ __forceinline__ void cpwait1()  { asm volatile("cp.async.wait_group 1;"); }

__device__ __forceinline__ void ins3(float s, int k,
                                     float& v0, float& v1, float& v2,
                                     int& k0, int& k1, int& k2) {
    if (s < v2) {
        if (s < v0)      { v2 = v1; k2 = k1; v1 = v0; k1 = k0; v0 = s; k0 = k; }
        else if (s < v1) { v2 = v1; k2 = k1; v1 = s;  k1 = k; }
        else             { v2 = s;  k2 = k; }
    }
}

__device__ __forceinline__ uint32_t s8x4(float a, float b, float c, float d) {
    int ia = __float2int_rn(fminf(fmaxf(a, -127.f), 127.f));
    int ib = __float2int_rn(fminf(fmaxf(b, -127.f), 127.f));
    int ic = __float2int_rn(fminf(fmaxf(c, -127.f), 127.f));
    int id = __float2int_rn(fminf(fmaxf(d, -127.f), 127.f));
    return (uint32_t)(ia & 0xff) | ((uint32_t)(ib & 0xff) << 8)
         | ((uint32_t)(ic & 0xff) << 16) | ((uint32_t)(id & 0xff) << 24);
}

// ---------------------------------------------------------------------------
// prep: codebook -> s8 (x 127*1024), code norms (fp32), reset loss counter
// ---------------------------------------------------------------------------
__global__ void prep_cb_kernel(const float* __restrict__ cb,
                               int8_t* __restrict__ cb8,
                               float* __restrict__ cbn, int* __restrict__ ctr)
{
    if (blockIdx.x == 0 && threadIdx.x == 0) *ctr = 0;
    int gw   = (blockIdx.x * blockDim.x + threadIdx.x) >> 5;
    int lane = threadIdx.x & 31;
    if (gw >= 1024) return;
    const float4* p = (const float4*)(cb + (size_t)gw * D_DIM);
    float4 v0 = p[lane * 2], v1 = p[lane * 2 + 1];
    float s = v0.x*v0.x + v0.y*v0.y + v0.z*v0.z + v0.w*v0.w
            + v1.x*v1.x + v1.y*v1.y + v1.z*v1.z + v1.w*v1.w;
#pragma unroll
    for (int o = 16; o > 0; o >>= 1) s += __shfl_xor_sync(0xffffffffu, s, o);
    if (lane == 0) cbn[gw] = s;
    const float ES = 130048.f;   // 127*1024
    uint2 u;
    u.x = s8x4(v0.x * ES, v0.y * ES, v0.z * ES, v0.w * ES);
    u.y = s8x4(v1.x * ES, v1.y * ES, v1.z * ES, v1.w * ES);
    *(uint2*)(cb8 + (size_t)gw * D_DIM + lane * 8) = u;
}

// ---------------------------------------------------------------------------
// coarse: s8 IMMA distance pass, top-8 candidates per row
//   block = 128 rows x 1024 codes (8 chunks of 128), 128-d slices (16 stages)
//   triple-buffered B ring, one barrier per stage
// ---------------------------------------------------------------------------
__global__ void __launch_bounds__(256, 2)
coarse_kernel(const float* __restrict__ x, const int8_t* __restrict__ cb8,
              const float* __restrict__ cbn, int* __restrict__ cand)
{
    extern __shared__ char sm[];
    const uint32_t smb = (uint32_t)__cvta_generic_to_shared(sm);

    const int tid  = threadIdx.x;
    const int lane = tid & 31, wid = tid >> 5;
    const int gid  = lane >> 2, tig = lane & 3;
    const int wm   = wid & 3, wn = wid >> 2;
    const int rm   = wm * 32;          // warp row base within block tile
    const int cnW  = wn * 64;          // warp col base within 128-code chunk
    const int rowBase = blockIdx.x * 128;

    const int lc = tid >> 1, lh = tid & 1;

    // stage A: x rows fp32 -> s8 (x 127/5), rows of 256B (16 units), swizzled
    {
        int r = tid >> 1, h = tid & 1;
        const float4* xp = (const float4*)(x + (size_t)(rowBase + r) * D_DIM + h * 128);
#pragma unroll
        for (int j = 0; j < 8; ++j) {
            float4 a0 = xp[4*j], a1 = xp[4*j+1], a2 = xp[4*j+2], a3 = xp[4*j+3];
            uint4 w;
            w.x = s8x4(a0.x * XSCALE, a0.y * XSCALE, a0.z * XSCALE, a0.w * XSCALE);
            w.y = s8x4(a1.x * XSCALE, a1.y * XSCALE, a1.z * XSCALE, a1.w * XSCALE);
            w.z = s8x4(a2.x * XSCALE, a2.y * XSCALE, a2.z * XSCALE, a2.w * XSCALE);
            w.w = s8x4(a3.x * XSCALE, a3.y * XSCALE, a3.z * XSCALE, a3.w * XSCALE);
            int u = h * 8 + j;                       // 16B unit (0..15)
            *(uint4*)(sm + r * 256 + ((u ^ (r & 7)) << 4)) = w;
        }
    }

    // B ring loader: stage t = (chunk t>>1, half t&1), 128 codes x 128B s8
    auto stage_load = [&](int t) {
        const int8_t* src =
            cb8 + (size_t)((t >> 1) * 128 + lc) * D_DIM + (t & 1) * 128;
        uint32_t dst = smb + OFF_B + (uint32_t)(t % 3) * 16384u + lc * 128;
#pragma unroll
        for (int j = 0; j < 4; ++j) {
            int u = lh * 4 + j;
            cpasync16(dst + ((u ^ (lc & 7)) << 4), src + u * 16);
        }
    };

    stage_load(0); cpcommit();
    stage_load(1); cpcommit();

    // candidate state: 4 row-slots x top-3
    float cv[4][3]; int ck[4][3];
#pragma unroll
    for (int i = 0; i < 4; ++i)
#pragma unroll
        for (int t = 0; t < 3; ++t) { cv[i][t] = FLT_BIG; ck[i][t] = 0; }

    int acc[2][8][4];
    const int m = lane >> 3, rr = lane & 7;

    for (int s = 0; s < 16; ++s) {
        cpwait1();
        __syncthreads();
        if (s + 2 < 16) stage_load(s + 2);
        cpcommit();

        const uint32_t bufb = smb + OFF_B + (uint32_t)(s % 3) * 16384u;

        if ((s & 1) == 0) {
#pragma unroll
            for (int mi = 0; mi < 2; ++mi)
#pragma unroll
                for (int nj = 0; nj < 8; ++nj)
#pragma unroll
                    for (int q = 0; q < 4; ++q) acc[mi][nj][q] = 0;
        }

#pragma unroll
        for (int ks = 0; ks < 4; ++ks) {          // k32 steps over the 128-d slice
            uint32_t a[2][4];
#pragma unroll
            for (int mi = 0; mi < 2; ++mi) {
                int row = rm + mi * 16 + (m & 1) * 8 + rr;
                int u = (s & 1) * 8 + ks * 2 + (m >> 1);
                ldsm4(smb + row * 256 + ((u ^ (row & 7)) << 4),
                      a[mi][0], a[mi][1], a[mi][2], a[mi][3]);
            }
#pragma unroll
            for (int nh = 0; nh < 2; ++nh) {
                uint32_t b[2][4];
#pragma unroll
                for (int g = 0; g < 2; ++g) {
                    int cr = cnW + nh * 32 + g * 16 + (m & 1) * 8 + rr;
                    int u = ks * 2 + (m >> 1);
                    ldsm4(bufb + cr * 128 + ((u ^ (cr & 7)) << 4),
                          b[g][0], b[g][1], b[g][2], b[g][3]);
                }
#pragma unroll
                for (int mi = 0; mi < 2; ++mi)
#pragma unroll
                    for (int g = 0; g < 2; ++g) {
                        int nj = nh * 4 + g * 2;
                        mma16832(acc[mi][nj],     a[mi], b[g][0], b[g][2]);
                        mma16832(acc[mi][nj + 1], a[mi], b[g][1], b[g][3]);
                    }
            }
        }

        if (s & 1) {   // chunk done: fold scores (descale int dot)
            const int kbase = (s >> 1) * 128 + cnW;
#pragma unroll
            for (int mi = 0; mi < 2; ++mi)
#pragma unroll
                for (int nj = 0; nj < 8; ++nj) {
                    int k0g = kbase + nj * 8 + 2 * tig;
                    float bn0 = __ldg(cbn + k0g), bn1 = __ldg(cbn + k0g + 1);
                    float s00 = fmaf(-DESCALE2, (float)acc[mi][nj][0], bn0);
                    float s01 = fmaf(-DESCALE2, (float)acc[mi][nj][1], bn1);
                    float s10 = fmaf(-DESCALE2, (float)acc[mi][nj][2], bn0);
                    float s11 = fmaf(-DESCALE2, (float)acc[mi][nj][3], bn1);
                    int r0 = mi * 2, r1 = mi * 2 + 1;
                    ins3(s00, k0g,     cv[r0][0], cv[r0][1], cv[r0][2], ck[r0][0], ck[r0][1], ck[r0][2]);
                    ins3(s01, k0g + 1, cv[r0][0], cv[r0][1], cv[r0][2], ck[r0][0], ck[r0][1], ck[r0][2]);
                    ins3(s10, k0g,     cv[r1][0], cv[r1][1], cv[r1][2], ck[r1][0], ck[r1][1], ck[r1][2]);
                    ins3(s11, k0g + 1, cv[r1][0], cv[r1][1], cv[r1][2], ck[r1][0], ck[r1][1], ck[r1][2]);
                }
        }
    }

    // merge: 8 owners x top-3 -> global top-8 per row (smem in B-ring region)
    __syncthreads();
    float* MV = (float*)(sm + OFF_B);
    int*   MK = (int*)(sm + OFF_B + 12288);
    const int owner = wn * 4 + tig;
#pragma unroll
    for (int ri = 0; ri < 4; ++ri) {
        int rloc = rm + (ri >> 1) * 16 + (ri & 1) * 8 + gid;
#pragma unroll
        for (int t = 0; t < 3; ++t) {
            MV[rloc * 24 + owner * 3 + t] = cv[ri][t];
            MK[rloc * 24 + owner * 3 + t] = ck[ri][t];
        }
    }
    __syncthreads();
    if (tid < 128) {
        float* mv = MV + tid * 24;
        int*   mk = MK + tid * 24;
#pragma unroll 1
        for (int t = 0; t < NCAND; ++t) {
            float bv = mv[0]; int bk = mk[0]; int bp = 0;
            for (int j = 1; j < 24; ++j) {
                float v = mv[j]; int kk = mk[j];
                if (v < bv || (v == bv && kk < bk)) { bv = v; bk = kk; bp = j; }
            }
            mv[bp] = FLT_BIG;
            cand[(size_t)(rowBase + tid) * NCAND + t] = bk;
        }
    }
}

// ---------------------------------------------------------------------------
// finalize: exact fp32 refine over 8 candidates + gather + loss (last block)
//   warp per row; 4 lanes per candidate
// ---------------------------------------------------------------------------
__global__ void __launch_bounds__(256)
finalize_kernel(const float* __restrict__ x, const float* __restrict__ cb,
                const float* __restrict__ cbn, const int* __restrict__ cand,
                float* __restrict__ outq, float* __restrict__ outidx,
                float* __restrict__ partial, float* __restrict__ lossOut,
                int* __restrict__ ctr, float inv)
{
    __shared__ float4 sxr[8][64];
    __shared__ float ssum[8];
    __shared__ int sflag;
    int tid = threadIdx.x, lane = tid & 31, wid = tid >> 5;
    int row = blockIdx.x * 8 + wid;

    const float4* xp = (const float4*)(x + (size_t)row * D_DIM);
    float4 v0 = xp[lane * 2], v1 = xp[lane * 2 + 1];
    sxr[wid][lane * 2] = v0;
    sxr[wid][lane * 2 + 1] = v1;
    float an = v0.x*v0.x + v0.y*v0.y + v0.z*v0.z + v0.w*v0.w
             + v1.x*v1.x + v1.y*v1.y + v1.z*v1.z + v1.w*v1.w;
#pragma unroll
    for (int o = 16; o > 0; o >>= 1) an += __shfl_xor_sync(0xffffffffu, an, o);
    __syncwarp();

    int ci = lane >> 2, q = lane & 3;
    int k = cand[(size_t)row * NCAND + ci];
    const float4* ep = (const float4*)(cb + (size_t)k * D_DIM);
    float acc = 0.f;
#pragma unroll
    for (int j = 0; j < 16; ++j) {
        float4 e  = ep[q + 4 * j];
        float4 xv = sxr[wid][q + 4 * j];
        acc = fmaf(xv.x, e.x, acc);
        acc = fmaf(xv.y, e.y, acc);
        acc = fmaf(xv.z, e.z, acc);
        acc = fmaf(xv.w, e.w, acc);
    }
    acc += __shfl_xor_sync(0xffffffffu, acc, 1);
    acc += __shfl_xor_sync(0xffffffffu, acc, 2);

    float t = an + cbn[k];
    float dist = t - 2.0f * acc;
#pragma unroll
    for (int o = 4; o <= 16; o <<= 1) {
        float d2 = __shfl_xor_sync(0xffffffffu, dist, o);
        int   k2 = __shfl_xor_sync(0xffffffffu, k, o);
        if (d2 < dist || (d2 == dist && k2 < k)) { dist = d2; k = k2; }
    }

    // gather + loss with the winning code
    const float4* cp = (const float4*)(cb + (size_t)k * D_DIM);
    float4* op = (float4*)(outq + (size_t)row * D_DIM);
    float4 q0 = cp[lane * 2], q1 = cp[lane * 2 + 1];
    op[lane * 2] = q0;
    op[lane * 2 + 1] = q1;
    float dx0 = q0.x - v0.x, dy0 = q0.y - v0.y, dz0 = q0.z - v0.z, dw0 = q0.w - v0.w;
    float dx1 = q1.x - v1.x, dy1 = q1.y - v1.y, dz1 = q1.z - v1.z, dw1 = q1.w - v1.w;
    float s = dx0*dx0 + dy0*dy0 + dz0*dz0 + dw0*dw0
            + dx1*dx1 + dy1*dy1 + dz1*dz1 + dw1*dw1;
#pragma unroll
    for (int o = 16; o > 0; o >>= 1) s += __shfl_xor_sync(0xffffffffu, s, o);
    if (lane == 0) {
        ssum[wid] = s;
        if (outidx) outidx[row] = (float)k;
    }
    __syncthreads();
    if (tid == 0) {
        float tt = 0.f;
        for (int i = 0; i < 8; ++i) tt += ssum[i];
        partial[blockIdx.x] = tt;
        __threadfence();
        int old = atomicAdd(ctr, 1);
        sflag = (old == (int)gridDim.x - 1);
    }
    __syncthreads();
    if (sflag) {
        // fixed-order deterministic reduction of all partials by the last block
        int nb = gridDim.x;
        float acc2 = 0.f;
        for (int i = tid; i < nb; i += 256) acc2 += __ldcg(partial + i);
#pragma unroll
        for (int o = 16; o > 0; o >>= 1) acc2 += __shfl_xor_sync(0xffffffffu, acc2, o);
        if (lane == 0) ssum[wid] = acc2;
        __syncthreads();
        if (tid == 0 && lossOut) {
            float tt = 0.f;
            for (int i = 0; i < 8; ++i) tt += ssum[i];
            *lossOut = tt * inv;
        }
    }
}

// ---------------------------------------------------------------------------
extern "C" void kernel_launch(void* const* d_in, const int* in_sizes, int n_in,
                              void* d_out, int out_size)
{
    const float* x  = (const float*)d_in[0];
    const float* cb = (const float*)d_in[1];
    int N = in_sizes[0] / D_DIM;   // 32768

    float* out  = (float*)d_out;
    float* outq = out;
    long long qn  = (long long)N * D_DIM;
    long long rem = (long long)out_size - qn;
    float* outidx  = nullptr;
    float* outloss = nullptr;
    if (rem >= (long long)N) {
        outidx = out + qn;
        if (rem >= (long long)N + 1) outloss = out + qn + N;
    } else if (rem >= 1) {
        outloss = out + qn;
    }

    int8_t* cb8; float *cbn, *part; int *cnd, *ctr;
    cudaGetSymbolAddress((void**)&cb8,  g_cb8);
    cudaGetSymbolAddress((void**)&cbn,  g_codenorm);
    cudaGetSymbolAddress((void**)&cnd,  g_cand);
    cudaGetSymbolAddress((void**)&part, g_partial);
    cudaGetSymbolAddress((void**)&ctr,  g_ctr);

    prep_cb_kernel<<<128, 256>>>(cb, cb8, cbn, ctr);

    cudaFuncSetAttribute(coarse_kernel,
                         cudaFuncAttributeMaxDynamicSharedMemorySize, CO_SMEM);
    coarse_kernel<<<N / 128, 256, CO_SMEM>>>(x, cb8, cbn, cnd);

    int fblocks = N / 8;
    finalize_kernel<<<fblocks, 256>>>(x, cb, cbn, cnd, outq, outidx, part,
                                      outloss, ctr,
                                      1.0f / (float)((long long)N * D_DIM));
}

// round 13
// speedup vs baseline: 1.4110x; 1.4110x over previous
#include <cuda_runtime.h>
#include <cuda_fp16.h>
#include <cstdint>

#define D_DIM 256
#define FLT_BIG 3.402823466e+38f
#define NCAND 4

// scratch (static device globals; no allocations)
__device__ __half g_cbh[1024 * 256];
__device__ float g_codenorm[1024];
__device__ int   g_cand[32768 * NCAND];
__device__ float g_partial[8192];
__device__ int   g_ctr;

// smem layout: A tile 64KB (fp16 128x256) | B ring 3x16KB
#define OFF_B   65536
#define CO_SMEM (65536 + 49152)   // 114688 -> 2 CTAs/SM (229376 <= 233472)

// ---------------------------------------------------------------------------
// PTX helpers (plain sm_103: mma.sync + ldmatrix + cp.async only)
// ---------------------------------------------------------------------------
__device__ __forceinline__ void ldsm4(uint32_t addr, uint32_t& r0, uint32_t& r1,
                                      uint32_t& r2, uint32_t& r3) {
    asm volatile("ldmatrix.sync.aligned.m8n8.x4.shared.b16 {%0,%1,%2,%3}, [%4];"
                 : "=r"(r0), "=r"(r1), "=r"(r2), "=r"(r3) : "r"(addr));
}
__device__ __forceinline__ void mma16816(float* c, const uint32_t* a,
                                         uint32_t b0, uint32_t b1) {
    asm volatile(
        "mma.sync.aligned.m16n8k16.row.col.f32.f16.f16.f32 "
        "{%0,%1,%2,%3}, {%4,%5,%6,%7}, {%8,%9}, {%0,%1,%2,%3};"
        : "+f"(c[0]), "+f"(c[1]), "+f"(c[2]), "+f"(c[3])
        : "r"(a[0]), "r"(a[1]), "r"(a[2]), "r"(a[3]), "r"(b0), "r"(b1));
}
__device__ __forceinline__ void cpasync16(uint32_t dst, const void* src) {
    asm volatile("cp.async.cg.shared.global [%0], [%1], 16;" :: "r"(dst), "l"(src));
}
__device__ __forceinline__ void cpcommit() { asm volatile("cp.async.commit_group;"); }
__device__ __forceinline__ void cpwait1()  { asm volatile("cp.async.wait_group 1;"); }

__device__ __forceinline__ void ins2(float s, int k,
                                     float& v0, float& v1, int& k0, int& k1) {
    if (s < v1) {
        if (s < v0) { v1 = v0; k1 = k0; v0 = s; k0 = k; }
        else        { v1 = s;  k1 = k; }
    }
}

__device__ __forceinline__ uint32_t h2u(float a, float b) {
    __half2 h = __float22half2_rn(make_float2(a, b));
    return *(uint32_t*)&h;
}

// ---------------------------------------------------------------------------
// prep: codebook -> fp16, code norms (fp32), reset loss counter
// ---------------------------------------------------------------------------
__global__ void prep_cb_kernel(const float* __restrict__ cb,
                               __half* __restrict__ cbh,
                               float* __restrict__ cbn, int* __restrict__ ctr)
{
    if (blockIdx.x == 0 && threadIdx.x == 0) *ctr = 0;
    int gw   = (blockIdx.x * blockDim.x + threadIdx.x) >> 5;
    int lane = threadIdx.x & 31;
    if (gw >= 1024) return;
    const float4* p = (const float4*)(cb + (size_t)gw * D_DIM);
    float4 v0 = p[lane * 2], v1 = p[lane * 2 + 1];
    float s = v0.x*v0.x + v0.y*v0.y + v0.z*v0.z + v0.w*v0.w
            + v1.x*v1.x + v1.y*v1.y + v1.z*v1.z + v1.w*v1.w;
#pragma unroll
    for (int o = 16; o > 0; o >>= 1) s += __shfl_xor_sync(0xffffffffu, s, o);
    if (lane == 0) cbn[gw] = s;
    uint4 u;
    u.x = h2u(v0.x, v0.y); u.y = h2u(v0.z, v0.w);
    u.z = h2u(v1.x, v1.y); u.w = h2u(v1.z, v1.w);
    *(uint4*)(cbh + (size_t)gw * D_DIM + lane * 8) = u;
}

// ---------------------------------------------------------------------------
// coarse: fp16 mma.sync distance pass, top-4 candidates per row
//   CTA: 512 threads, 128 rows x 1024 codes (8 chunks of 128), d-slices of 64
//   warp grid 4x4, warp tile 32 rows x 32 cols; 8 warps/SMSP at 2 CTAs/SM
//   triple-buffered B ring, one barrier per stage
// ---------------------------------------------------------------------------
__global__ void __launch_bounds__(512, 2)
coarse_kernel(const float* __restrict__ x, const __half* __restrict__ cbh,
              const float* __restrict__ cbn, int* __restrict__ cand)
{
    extern __shared__ char sm[];
    const uint32_t smb = (uint32_t)__cvta_generic_to_shared(sm);

    const int tid  = threadIdx.x;
    const int lane = tid & 31, wid = tid >> 5;
    const int gid  = lane >> 2, tig = lane & 3;
    const int wm   = wid & 3, wn = wid >> 2;      // 4 x 4 warp grid
    const int rm   = wm * 32;          // warp row base within 128-row tile
    const int cnW  = wn * 32;          // warp col base within 128-code chunk
    const int rowBase = blockIdx.x * 128;

    const int lc = tid >> 2, lq = tid & 3;   // B loads: code row, quarter

    // stage A: x tile 128 rows x 256 d, fp32 -> fp16, 512B rows, swizzled
    {
        int r = tid >> 2, h = tid & 3;
        const float4* xp = (const float4*)(x + (size_t)(rowBase + r) * D_DIM + h * 64);
#pragma unroll
        for (int j = 0; j < 8; ++j) {
            float4 v0 = xp[2 * j], v1 = xp[2 * j + 1];
            uint4 u;
            u.x = h2u(v0.x, v0.y); u.y = h2u(v0.z, v0.w);
            u.z = h2u(v1.x, v1.y); u.w = h2u(v1.z, v1.w);
            int ui = h * 8 + j;                      // 16B unit (0..31)
            *(uint4*)(sm + r * 512 + ((ui ^ (r & 7)) << 4)) = u;
        }
    }

    // B ring loader for stage t (buf = t % 3), 64-d slice of a 128-code chunk
    auto stage_load = [&](int t) {
        const __half* src =
            cbh + (size_t)((t >> 2) * 128 + lc) * D_DIM + (t & 3) * 64;
        uint32_t dst = smb + OFF_B + (uint32_t)(t % 3) * 16384u + lc * 128;
#pragma unroll
        for (int j = 0; j < 2; ++j) {
            int u = lq * 2 + j;
            cpasync16(dst + ((u ^ (lc & 7)) << 4), src + u * 8);
        }
    };

    stage_load(0); cpcommit();
    stage_load(1); cpcommit();

    // candidate state: 4 row-slots x top-2
    float cv[4][2]; int ck[4][2];
#pragma unroll
    for (int i = 0; i < 4; ++i) {
        cv[i][0] = FLT_BIG; cv[i][1] = FLT_BIG; ck[i][0] = 0; ck[i][1] = 0;
    }

    float acc[2][4][4];
    const int m = lane >> 3, rr = lane & 7;

    for (int s = 0; s < 32; ++s) {
        cpwait1();            // group s complete
        __syncthreads();      // buffer s visible, stage s-1 compute done
        if (s + 2 < 32) stage_load(s + 2);
        cpcommit();

        const int chunk = s >> 2, ds = s & 3;
        const uint32_t bufb = smb + OFF_B + (uint32_t)(s % 3) * 16384u;

        if (ds == 0) {
#pragma unroll
            for (int mi = 0; mi < 2; ++mi)
#pragma unroll
                for (int nj = 0; nj < 4; ++nj)
#pragma unroll
                    for (int q = 0; q < 4; ++q) acc[mi][nj][q] = 0.f;
        }

#pragma unroll
        for (int ks = 0; ks < 4; ++ks) {
            uint32_t a[2][4];
#pragma unroll
            for (int mi = 0; mi < 2; ++mi) {
                int row = rm + mi * 16 + (m & 1) * 8 + rr;
                int u = ds * 8 + ks * 2 + (m >> 1);
                ldsm4(smb + row * 512 + ((u ^ (row & 7)) << 4),
                      a[mi][0], a[mi][1], a[mi][2], a[mi][3]);
            }
            uint32_t b[2][4];
#pragma unroll
            for (int g = 0; g < 2; ++g) {
                int cr = cnW + g * 16 + (m & 1) * 8 + rr;
                int u = ks * 2 + (m >> 1);
                ldsm4(bufb + cr * 128 + ((u ^ (cr & 7)) << 4),
                      b[g][0], b[g][1], b[g][2], b[g][3]);
            }
#pragma unroll
            for (int mi = 0; mi < 2; ++mi)
#pragma unroll
                for (int g = 0; g < 2; ++g) {
                    int nj = g * 2;
                    mma16816(acc[mi][nj],     a[mi], b[g][0], b[g][2]);
                    mma16816(acc[mi][nj + 1], a[mi], b[g][1], b[g][3]);
                }
        }

        if (ds == 3) {   // chunk done: fold scores into top-2 per row-slot
            const int kbase = chunk * 128 + cnW;
#pragma unroll
            for (int mi = 0; mi < 2; ++mi)
#pragma unroll
                for (int nj = 0; nj < 4; ++nj) {
                    int k0g = kbase + nj * 8 + 2 * tig;
                    float bn0 = __ldg(cbn + k0g), bn1 = __ldg(cbn + k0g + 1);
                    float s00 = fmaf(-2.f, acc[mi][nj][0], bn0);
                    float s01 = fmaf(-2.f, acc[mi][nj][1], bn1);
                    float s10 = fmaf(-2.f, acc[mi][nj][2], bn0);
                    float s11 = fmaf(-2.f, acc[mi][nj][3], bn1);
                    int r0 = mi * 2, r1 = mi * 2 + 1;
                    ins2(s00, k0g,     cv[r0][0], cv[r0][1], ck[r0][0], ck[r0][1]);
                    ins2(s01, k0g + 1, cv[r0][0], cv[r0][1], ck[r0][0], ck[r0][1]);
                    ins2(s10, k0g,     cv[r1][0], cv[r1][1], ck[r1][0], ck[r1][1]);
                    ins2(s11, k0g + 1, cv[r1][0], cv[r1][1], ck[r1][0], ck[r1][1]);
                }
        }
    }

    // merge: 16 owners x top-2 -> global top-4 per row (smem in B-ring region)
    __syncthreads();
    float* MV = (float*)(sm + OFF_B);              // [128][32]
    int*   MK = (int*)(sm + OFF_B + 16384);        // [128][32]
    const int owner = wn * 4 + tig;
#pragma unroll
    for (int ri = 0; ri < 4; ++ri) {
        int rloc = rm + (ri >> 1) * 16 + (ri & 1) * 8 + gid;
        MV[rloc * 32 + owner * 2 + 0] = cv[ri][0];
        MV[rloc * 32 + owner * 2 + 1] = cv[ri][1];
        MK[rloc * 32 + owner * 2 + 0] = ck[ri][0];
        MK[rloc * 32 + owner * 2 + 1] = ck[ri][1];
    }
    __syncthreads();
    if (tid < 128) {
        float* mv = MV + tid * 32;
        int*   mk = MK + tid * 32;
#pragma unroll 1
        for (int t = 0; t < NCAND; ++t) {
            float bv = mv[0]; int bk = mk[0]; int bp = 0;
            for (int j = 1; j < 32; ++j) {
                float v = mv[j]; int kk = mk[j];
                if (v < bv || (v == bv && kk < bk)) { bv = v; bk = kk; bp = j; }
            }
            mv[bp] = FLT_BIG;
            cand[(size_t)(rowBase + tid) * NCAND + t] = bk;
        }
    }
}

// ---------------------------------------------------------------------------
// finalize: exact fp32 refine over 4 candidates + gather + loss (last block)
//   warp per row; 8 lanes per candidate
// ---------------------------------------------------------------------------
__global__ void __launch_bounds__(256)
finalize_kernel(const float* __restrict__ x, const float* __restrict__ cb,
                const float* __restrict__ cbn, const int* __restrict__ cand,
                float* __restrict__ outq, float* __restrict__ outidx,
                float* __restrict__ partial, float* __restrict__ lossOut,
                int* __restrict__ ctr, float inv)
{
    __shared__ float4 sxr[8][64];
    __shared__ float ssum[8];
    __shared__ int sflag;
    int tid = threadIdx.x, lane = tid & 31, wid = tid >> 5;
    int row = blockIdx.x * 8 + wid;

    const float4* xp = (const float4*)(x + (size_t)row * D_DIM);
    float4 v0 = xp[lane * 2], v1 = xp[lane * 2 + 1];
    sxr[wid][lane * 2] = v0;
    sxr[wid][lane * 2 + 1] = v1;
    float an = v0.x*v0.x + v0.y*v0.y + v0.z*v0.z + v0.w*v0.w
             + v1.x*v1.x + v1.y*v1.y + v1.z*v1.z + v1.w*v1.w;
#pragma unroll
    for (int o = 16; o > 0; o >>= 1) an += __shfl_xor_sync(0xffffffffu, an, o);
    __syncwarp();

    int ci = lane >> 3, q = lane & 7;
    int k = cand[(size_t)row * NCAND + ci];
    const float4* ep = (const float4*)(cb + (size_t)k * D_DIM);
    float acc = 0.f;
#pragma unroll
    for (int j = 0; j < 8; ++j) {
        float4 e  = ep[q + 8 * j];
        float4 xv = sxr[wid][q + 8 * j];
        acc = fmaf(xv.x, e.x, acc);
        acc = fmaf(xv.y, e.y, acc);
        acc = fmaf(xv.z, e.z, acc);
        acc = fmaf(xv.w, e.w, acc);
    }
    acc += __shfl_xor_sync(0xffffffffu, acc, 1);
    acc += __shfl_xor_sync(0xffffffffu, acc, 2);
    acc += __shfl_xor_sync(0xffffffffu, acc, 4);

    float t = an + cbn[k];
    float dist = t - 2.0f * acc;
#pragma unroll
    for (int o = 8; o <= 16; o <<= 1) {
        float d2 = __shfl_xor_sync(0xffffffffu, dist, o);
        int   k2 = __shfl_xor_sync(0xffffffffu, k, o);
        if (d2 < dist || (d2 == dist && k2 < k)) { dist = d2; k = k2; }
    }

    // gather + loss with the winning code
    const float4* cp = (const float4*)(cb + (size_t)k * D_DIM);
    float4* op = (float4*)(outq + (size_t)row * D_DIM);
    float4 q0 = cp[lane * 2], q1 = cp[lane * 2 + 1];
    op[lane * 2] = q0;
    op[lane * 2 + 1] = q1;
    float dx0 = q0.x - v0.x, dy0 = q0.y - v0.y, dz0 = q0.z - v0.z, dw0 = q0.w - v0.w;
    float dx1 = q1.x - v1.x, dy1 = q1.y - v1.y, dz1 = q1.z - v1.z, dw1 = q1.w - v1.w;
    float s = dx0*dx0 + dy0*dy0 + dz0*dz0 + dw0*dw0
            + dx1*dx1 + dy1*dy1 + dz1*dz1 + dw1*dw1;
#pragma unroll
    for (int o = 16; o > 0; o >>= 1) s += __shfl_xor_sync(0xffffffffu, s, o);
    if (lane == 0) {
        ssum[wid] = s;
        if (outidx) outidx[row] = (float)k;
    }
    __syncthreads();
    if (tid == 0) {
        float tt = 0.f;
        for (int i = 0; i < 8; ++i) tt += ssum[i];
        partial[blockIdx.x] = tt;
        __threadfence();
        int old = atomicAdd(ctr, 1);
        sflag = (old == (int)gridDim.x - 1);
    }
    __syncthreads();
    if (sflag) {
        int nb = gridDim.x;
        float acc2 = 0.f;
        for (int i = tid; i < nb; i += 256) acc2 += __ldcg(partial + i);
#pragma unroll
        for (int o = 16; o > 0; o >>= 1) acc2 += __shfl_xor_sync(0xffffffffu, acc2, o);
        if (lane == 0) ssum[wid] = acc2;
        __syncthreads();
        if (tid == 0 && lossOut) {
            float tt = 0.f;
            for (int i = 0; i < 8; ++i) tt += ssum[i];
            *lossOut = tt * inv;
        }
    }
}

// ---------------------------------------------------------------------------
extern "C" void kernel_launch(void* const* d_in, const int* in_sizes, int n_in,
                              void* d_out, int out_size)
{
    const float* x  = (const float*)d_in[0];
    const float* cb = (const float*)d_in[1];
    int N = in_sizes[0] / D_DIM;   // 32768

    float* out  = (float*)d_out;
    float* outq = out;
    long long qn  = (long long)N * D_DIM;
    long long rem = (long long)out_size - qn;
    float* outidx  = nullptr;
    float* outloss = nullptr;
    if (rem >= (long long)N) {
        outidx = out + qn;
        if (rem >= (long long)N + 1) outloss = out + qn + N;
    } else if (rem >= 1) {
        outloss = out + qn;
    }

    __half* cbh; float *cbn, *part; int *cnd, *ctr;
    cudaGetSymbolAddress((void**)&cbh,  g_cbh);
    cudaGetSymbolAddress((void**)&cbn,  g_codenorm);
    cudaGetSymbolAddress((void**)&cnd,  g_cand);
    cudaGetSymbolAddress((void**)&part, g_partial);
    cudaGetSymbolAddress((void**)&ctr,  g_ctr);

    prep_cb_kernel<<<128, 256>>>(cb, cbh, cbn, ctr);

    cudaFuncSetAttribute(coarse_kernel,
                         cudaFuncAttributeMaxDynamicSharedMemorySize, CO_SMEM);
    coarse_kernel<<<N / 128, 512, CO_SMEM>>>(x, cbh, cbn, cnd);

    int fblocks = N / 8;
    finalize_kernel<<<fblocks, 256>>>(x, cb, cbn, cnd, outq, outidx, part,
                                      outloss, ctr,
                                      1.0f / (float)((long long)N * D_DIM));
}

// round 15
// speedup vs baseline: 1.6428x; 1.1642x over previous
#include <cuda_runtime.h>
#include <cuda_bf16.h>
#include <cstdint>

#define D_DIM 256
#define FLT_BIG 3.402823466e+38f
#define NCAND 4

// scratch (static device globals; no allocations)
__device__ __nv_bfloat16 g_cbb[1024 * 256];
__device__ float g_codenorm[1024];
__device__ float g_partial[512];
__device__ int   g_ctr;

// smem layout: A tile 64KB | B ring 3x16KB (reused by merge/refine tail)
#define OFF_B   65536
#define CO_SMEM (65536 + 49152)   // 114688 -> 2 CTAs/SM

// tail-phase smem offsets (inside the B-ring region, dead after main loop)
#define OFF_MV   OFF_B              // 128*24 floats = 12288
#define OFF_MK   (OFF_B + 12288)    // 128*24 ints   = 12288
#define OFF_CSR  (OFF_B + 24576)    // candS 128*4 ints = 2048
#define OFF_XS   (OFF_B + 26624)    // 8 warps * 64 float4 = 8192
#define OFF_LS   (OFF_B + 34816)    // ssum[8] + flag

// ---------------------------------------------------------------------------
// PTX helpers (plain sm_103: mma.sync + ldmatrix + cp.async only)
// ---------------------------------------------------------------------------
__device__ __forceinline__ void ldsm4(uint32_t addr, uint32_t& r0, uint32_t& r1,
                                      uint32_t& r2, uint32_t& r3) {
    asm volatile("ldmatrix.sync.aligned.m8n8.x4.shared.b16 {%0,%1,%2,%3}, [%4];"
                 : "=r"(r0), "=r"(r1), "=r"(r2), "=r"(r3) : "r"(addr));
}
__device__ __forceinline__ void mma16816(float* c, const uint32_t* a,
                                         uint32_t b0, uint32_t b1) {
    asm volatile(
        "mma.sync.aligned.m16n8k16.row.col.f32.bf16.bf16.f32 "
        "{%0,%1,%2,%3}, {%4,%5,%6,%7}, {%8,%9}, {%0,%1,%2,%3};"
        : "+f"(c[0]), "+f"(c[1]), "+f"(c[2]), "+f"(c[3])
        : "r"(a[0]), "r"(a[1]), "r"(a[2]), "r"(a[3]), "r"(b0), "r"(b1));
}
__device__ __forceinline__ void cpasync16(uint32_t dst, const void* src) {
    asm volatile("cp.async.cg.shared.global [%0], [%1], 16;" :: "r"(dst), "l"(src));
}
__device__ __forceinline__ void cpcommit() { asm volatile("cp.async.commit_group;"); }
__device__ __forceinline__ void cpwait1()  { asm volatile("cp.async.wait_group 1;"); }

__device__ __forceinline__ void ins3(float s, int k,
                                     float& v0, float& v1, float& v2,
                                     int& k0, int& k1, int& k2) {
    if (s < v2) {
        if (s < v0)      { v2 = v1; k2 = k1; v1 = v0; k1 = k0; v0 = s; k0 = k; }
        else if (s < v1) { v2 = v1; k2 = k1; v1 = s;  k1 = k; }
        else             { v2 = s;  k2 = k; }
    }
}

// ---------------------------------------------------------------------------
// prep: codebook -> bf16, code norms (fp32), reset loss counter
// ---------------------------------------------------------------------------
__global__ void prep_cb_kernel(const float* __restrict__ cb,
                               __nv_bfloat16* __restrict__ cbb,
                               float* __restrict__ cbn, int* __restrict__ ctr)
{
    if (blockIdx.x == 0 && threadIdx.x == 0) *ctr = 0;
    int gw   = (blockIdx.x * blockDim.x + threadIdx.x) >> 5;
    int lane = threadIdx.x & 31;
    if (gw >= 1024) return;
    const float4* p = (const float4*)(cb + (size_t)gw * D_DIM);
    float4 v0 = p[lane * 2], v1 = p[lane * 2 + 1];
    float s = v0.x*v0.x + v0.y*v0.y + v0.z*v0.z + v0.w*v0.w
            + v1.x*v1.x + v1.y*v1.y + v1.z*v1.z + v1.w*v1.w;
#pragma unroll
    for (int o = 16; o > 0; o >>= 1) s += __shfl_xor_sync(0xffffffffu, s, o);
    if (lane == 0) cbn[gw] = s;
    __nv_bfloat162 b0 = __floats2bfloat162_rn(v0.x, v0.y);
    __nv_bfloat162 b1 = __floats2bfloat162_rn(v0.z, v0.w);
    __nv_bfloat162 b2 = __floats2bfloat162_rn(v1.x, v1.y);
    __nv_bfloat162 b3 = __floats2bfloat162_rn(v1.z, v1.w);
    uint4 u;
    u.x = *(uint32_t*)&b0; u.y = *(uint32_t*)&b1;
    u.z = *(uint32_t*)&b2; u.w = *(uint32_t*)&b3;
    *(uint4*)(cbb + (size_t)gw * D_DIM + lane * 8) = u;
}

// ---------------------------------------------------------------------------
// fused kernel: bf16 mma.sync coarse top-4  +  exact fp32 refine + gather +
// loss — one launch, candidates never leave the CTA.
//   block = 256 threads, 128 rows x 1024 codes (8 chunks of 128), 64-d slices
//   triple-buffered B ring, one barrier per stage (proven R8 shape)
// ---------------------------------------------------------------------------
__global__ void __launch_bounds__(256, 2)
vq_fused_kernel(const float* __restrict__ x, const __nv_bfloat16* __restrict__ cbb,
                const float* __restrict__ cbn, const float* __restrict__ cb,
                float* __restrict__ outq, float* __restrict__ outidx,
                float* __restrict__ partial, float* __restrict__ lossOut,
                int* __restrict__ ctr, float inv)
{
    extern __shared__ char sm[];
    const uint32_t smb = (uint32_t)__cvta_generic_to_shared(sm);

    const int tid  = threadIdx.x;
    const int lane = tid & 31, wid = tid >> 5;
    const int gid  = lane >> 2, tig = lane & 3;
    const int wm   = wid & 3, wn = wid >> 2;
    const int rm   = wm * 32;          // warp row base within block tile
    const int cnW  = wn * 64;          // warp col base within 128-code chunk
    const int rowBase = blockIdx.x * 128;

    const int lc = tid >> 1, lh = tid & 1;   // B loads: code row, half

    // stage x tile: 128 rows x 256 d, fp32 -> bf16, swizzled 16B units
    {
        int r = tid >> 1, h = tid & 1;
        const float4* xp = (const float4*)(x + (size_t)(rowBase + r) * D_DIM + h * 128);
#pragma unroll
        for (int j = 0; j < 16; ++j) {
            float4 v0 = xp[2 * j], v1 = xp[2 * j + 1];
            __nv_bfloat162 p0 = __floats2bfloat162_rn(v0.x, v0.y);
            __nv_bfloat162 p1 = __floats2bfloat162_rn(v0.z, v0.w);
            __nv_bfloat162 p2 = __floats2bfloat162_rn(v1.x, v1.y);
            __nv_bfloat162 p3 = __floats2bfloat162_rn(v1.z, v1.w);
            uint4 u;
            u.x = *(uint32_t*)&p0; u.y = *(uint32_t*)&p1;
            u.z = *(uint32_t*)&p2; u.w = *(uint32_t*)&p3;
            int ui = h * 16 + j;
            *(uint4*)(sm + r * 512 + ((ui ^ (r & 7)) << 4)) = u;
        }
    }

    // B ring loader for stage t (buf = t % 3), 64-d slice of a 128-code chunk
    auto stage_load = [&](int t) {
        const __nv_bfloat16* src =
            cbb + (size_t)((t >> 2) * 128 + lc) * D_DIM + (t & 3) * 64;
        uint32_t dst = smb + OFF_B + (uint32_t)(t % 3) * 16384u + lc * 128;
#pragma unroll
        for (int j = 0; j < 4; ++j) {
            int u = lh * 4 + j;
            cpasync16(dst + ((u ^ (lc & 7)) << 4), src + u * 8);
        }
    };

    stage_load(0); cpcommit();
    stage_load(1); cpcommit();

    // candidate state: 4 row-slots x top-3
    float cv[4][3]; int ck[4][3];
#pragma unroll
    for (int i = 0; i < 4; ++i)
#pragma unroll
        for (int t = 0; t < 3; ++t) { cv[i][t] = FLT_BIG; ck[i][t] = 0; }

    float acc[2][8][4];
    const int m = lane >> 3, rr = lane & 7;

    for (int s = 0; s < 32; ++s) {
        cpwait1();            // group s complete (pending <= group s+1)
        __syncthreads();      // all warps: buffer s visible, stage s-1 compute done
        if (s + 2 < 32) stage_load(s + 2);   // buf (s+2)%3 == (s-1)%3: free now
        cpcommit();

        const int chunk = s >> 2, ds = s & 3;
        const uint32_t bufb = smb + OFF_B + (uint32_t)(s % 3) * 16384u;

        if (ds == 0) {
#pragma unroll
            for (int mi = 0; mi < 2; ++mi)
#pragma unroll
                for (int nj = 0; nj < 8; ++nj)
#pragma unroll
                    for (int q = 0; q < 4; ++q) acc[mi][nj][q] = 0.f;
        }

#pragma unroll
        for (int ks = 0; ks < 4; ++ks) {
            uint32_t a[2][4];
#pragma unroll
            for (int mi = 0; mi < 2; ++mi) {
                int row = rm + mi * 16 + (m & 1) * 8 + rr;
                int u = ds * 8 + ks * 2 + (m >> 1);
                ldsm4(smb + row * 512 + ((u ^ (row & 7)) << 4),
                      a[mi][0], a[mi][1], a[mi][2], a[mi][3]);
            }
#pragma unroll
            for (int nh = 0; nh < 2; ++nh) {
                uint32_t b[2][4];
#pragma unroll
                for (int g = 0; g < 2; ++g) {
                    int cr = cnW + nh * 32 + g * 16 + (m & 1) * 8 + rr;
                    int u = ks * 2 + (m >> 1);
                    ldsm4(bufb + cr * 128 + ((u ^ (cr & 7)) << 4),
                          b[g][0], b[g][1], b[g][2], b[g][3]);
                }
#pragma unroll
                for (int mi = 0; mi < 2; ++mi)
#pragma unroll
                    for (int g = 0; g < 2; ++g) {
                        int nj = nh * 4 + g * 2;
                        mma16816(acc[mi][nj],     a[mi], b[g][0], b[g][2]);
                        mma16816(acc[mi][nj + 1], a[mi], b[g][1], b[g][3]);
                    }
            }
        }

        if (ds == 3) {   // chunk done: fold scores into top-3 per row-slot
            const int kbase = chunk * 128 + cnW;
#pragma unroll
            for (int mi = 0; mi < 2; ++mi)
#pragma unroll
                for (int nj = 0; nj < 8; ++nj) {
                    int k0g = kbase + nj * 8 + 2 * tig;
                    float bn0 = __ldg(cbn + k0g), bn1 = __ldg(cbn + k0g + 1);
                    float s00 = fmaf(-2.f, acc[mi][nj][0], bn0);
                    float s01 = fmaf(-2.f, acc[mi][nj][1], bn1);
                    float s10 = fmaf(-2.f, acc[mi][nj][2], bn0);
                    float s11 = fmaf(-2.f, acc[mi][nj][3], bn1);
                    int r0 = mi * 2, r1 = mi * 2 + 1;
                    ins3(s00, k0g,     cv[r0][0], cv[r0][1], cv[r0][2], ck[r0][0], ck[r0][1], ck[r0][2]);
                    ins3(s01, k0g + 1, cv[r0][0], cv[r0][1], cv[r0][2], ck[r0][0], ck[r0][1], ck[r0][2]);
                    ins3(s10, k0g,     cv[r1][0], cv[r1][1], cv[r1][2], ck[r1][0], ck[r1][1], ck[r1][2]);
                    ins3(s11, k0g + 1, cv[r1][0], cv[r1][1], cv[r1][2], ck[r1][0], ck[r1][1], ck[r1][2]);
                }
        }
    }

    // ---- merge: 8 owners x top-3 -> top-4 per row, kept in SMEM ----
    __syncthreads();
    float* MV = (float*)(sm + OFF_MV);
    int*   MK = (int*)(sm + OFF_MK);
    int*   candS = (int*)(sm + OFF_CSR);
    const int owner = wn * 4 + tig;
#pragma unroll
    for (int ri = 0; ri < 4; ++ri) {
        int rloc = rm + (ri >> 1) * 16 + (ri & 1) * 8 + gid;
#pragma unroll
        for (int t = 0; t < 3; ++t) {
            MV[rloc * 24 + owner * 3 + t] = cv[ri][t];
            MK[rloc * 24 + owner * 3 + t] = ck[ri][t];
        }
    }
    __syncthreads();
    if (tid < 128) {
        float* mv = MV + tid * 24;
        int*   mk = MK + tid * 24;
#pragma unroll 1
        for (int t = 0; t < NCAND; ++t) {
            float bv = mv[0]; int bk = mk[0]; int bp = 0;
            for (int j = 1; j < 24; ++j) {
                float v = mv[j]; int kk = mk[j];
                if (v < bv || (v == bv && kk < bk)) { bv = v; bk = kk; bp = j; }
            }
            mv[bp] = FLT_BIG;
            candS[tid * NCAND + t] = bk;
        }
    }
    __syncthreads();

    // ---- refine + gather + loss: 8 warps x 16 rows (finalize arithmetic) ----
    float4* xs = (float4*)(sm + OFF_XS) + wid * 64;   // per-warp 1KB x-row stage
    float* ssumL = (float*)(sm + OFF_LS);
    float wl = 0.f;

#pragma unroll 1
    for (int i = 0; i < 16; ++i) {
        int r = wid * 16 + i;
        int row = rowBase + r;

        const float4* xp = (const float4*)(x + (size_t)row * D_DIM);
        float4 v0 = xp[lane * 2], v1 = xp[lane * 2 + 1];
        xs[lane * 2] = v0;
        xs[lane * 2 + 1] = v1;
        float an = v0.x*v0.x + v0.y*v0.y + v0.z*v0.z + v0.w*v0.w
                 + v1.x*v1.x + v1.y*v1.y + v1.z*v1.z + v1.w*v1.w;
#pragma unroll
        for (int o = 16; o > 0; o >>= 1) an += __shfl_xor_sync(0xffffffffu, an, o);
        __syncwarp();

        int ci = lane >> 3, q = lane & 7;
        int k = candS[r * NCAND + ci];
        const float4* ep = (const float4*)(cb + (size_t)k * D_DIM);
        float acc2 = 0.f;
#pragma unroll
        for (int j = 0; j < 8; ++j) {
            float4 e  = ep[q + 8 * j];
            float4 xv = xs[q + 8 * j];
            acc2 = fmaf(xv.x, e.x, acc2);
            acc2 = fmaf(xv.y, e.y, acc2);
            acc2 = fmaf(xv.z, e.z, acc2);
            acc2 = fmaf(xv.w, e.w, acc2);
        }
        acc2 += __shfl_xor_sync(0xffffffffu, acc2, 1);
        acc2 += __shfl_xor_sync(0xffffffffu, acc2, 2);
        acc2 += __shfl_xor_sync(0xffffffffu, acc2, 4);

        float t = an + cbn[k];
        float dist = t - 2.0f * acc2;
#pragma unroll
        for (int o = 8; o <= 16; o <<= 1) {
            float d2 = __shfl_xor_sync(0xffffffffu, dist, o);
            int   k2 = __shfl_xor_sync(0xffffffffu, k, o);
            if (d2 < dist || (d2 == dist && k2 < k)) { dist = d2; k = k2; }
        }

        // gather + loss with the winning code
        const float4* cp = (const float4*)(cb + (size_t)k * D_DIM);
        float4* op = (float4*)(outq + (size_t)row * D_DIM);
        float4 q0 = cp[lane * 2], q1 = cp[lane * 2 + 1];
        op[lane * 2] = q0;
        op[lane * 2 + 1] = q1;
        float dx0 = q0.x - v0.x, dy0 = q0.y - v0.y, dz0 = q0.z - v0.z, dw0 = q0.w - v0.w;
        float dx1 = q1.x - v1.x, dy1 = q1.y - v1.y, dz1 = q1.z - v1.z, dw1 = q1.w - v1.w;
        float s = dx0*dx0 + dy0*dy0 + dz0*dz0 + dw0*dw0
                + dx1*dx1 + dy1*dy1 + dz1*dz1 + dw1*dw1;
#pragma unroll
        for (int o = 16; o > 0; o >>= 1) s += __shfl_xor_sync(0xffffffffu, s, o);
        if (lane == 0) {
            wl += s;
            if (outidx) outidx[row] = (float)k;
        }
        __syncwarp();
    }

    if (lane == 0) ssumL[wid] = wl;
    __syncthreads();
    __shared__ int sflag;
    if (tid == 0) {
        float tt = 0.f;
        for (int i = 0; i < 8; ++i) tt += ssumL[i];
        partial[blockIdx.x] = tt;
        __threadfence();
        int old = atomicAdd(ctr, 1);
        sflag = (old == (int)gridDim.x - 1);
    }
    __syncthreads();
    if (sflag) {
        // fixed-order deterministic reduction of all partials by the last CTA
        int nb = gridDim.x;
        float a2 = 0.f;
        for (int i = tid; i < nb; i += 256) a2 += __ldcg(partial + i);
#pragma unroll
        for (int o = 16; o > 0; o >>= 1) a2 += __shfl_xor_sync(0xffffffffu, a2, o);
        if (lane == 0) ssumL[wid] = a2;
        __syncthreads();
        if (tid == 0 && lossOut) {
            float tt = 0.f;
            for (int i = 0; i < 8; ++i) tt += ssumL[i];
            *lossOut = tt * inv;
        }
    }
}

// ---------------------------------------------------------------------------
extern "C" void kernel_launch(void* const* d_in, const int* in_sizes, int n_in,
                              void* d_out, int out_size)
{
    const float* x  = (const float*)d_in[0];
    const float* cb = (const float*)d_in[1];
    int N = in_sizes[0] / D_DIM;   // 32768

    float* out  = (float*)d_out;
    float* outq = out;
    long long qn  = (long long)N * D_DIM;
    long long rem = (long long)out_size - qn;
    float* outidx  = nullptr;
    float* outloss = nullptr;
    if (rem >= (long long)N) {
        outidx = out + qn;
        if (rem >= (long long)N + 1) outloss = out + qn + N;
    } else if (rem >= 1) {
        outloss = out + qn;
    }

    __nv_bfloat16* cbb; float *cbn, *part; int *ctr;
    cudaGetSymbolAddress((void**)&cbb,  g_cbb);
    cudaGetSymbolAddress((void**)&cbn,  g_codenorm);
    cudaGetSymbolAddress((void**)&part, g_partial);
    cudaGetSymbolAddress((void**)&ctr,  g_ctr);

    prep_cb_kernel<<<128, 256>>>(cb, cbb, cbn, ctr);

    cudaFuncSetAttribute(vq_fused_kernel,
                         cudaFuncAttributeMaxDynamicSharedMemorySize, CO_SMEM);
    vq_fused_kernel<<<N / 128, 256, CO_SMEM>>>(x, cbb, cbn, cb, outq, outidx,
                                               part, outloss, ctr,
                                               1.0f / (float)((long long)N * D_DIM));
}

// round 16
// speedup vs baseline: 1.7187x; 1.0462x over previous
#include <cuda_runtime.h>
#include <cuda_bf16.h>
#include <cstdint>

#define D_DIM 256
#define FLT_BIG 3.402823466e+38f
#define NCAND 4
#define U32_BIG 0xFFFFFFFFu

// scratch (static device globals; no allocations)
__device__ __nv_bfloat16 g_cbb[1024 * 256];
__device__ float g_codenorm[1024];     // raw ||e||^2 (refine)
__device__ float g_codenormb[1024];    // ||e||^2 + 2.0f (coarse, packed-score bias)
__device__ float g_partial[512];
__device__ int   g_ctr;

// smem layout: A tile 64KB | B ring 3x16KB (reused by merge/refine tail)
#define OFF_B   65536
#define CO_SMEM (65536 + 49152)   // 114688 -> 2 CTAs/SM

// tail-phase smem offsets (inside the B-ring region, dead after main loop)
#define OFF_MU   OFF_B              // 128*24 u32 = 12288
#define OFF_CSR  (OFF_B + 12288)    // candS 128*4 ints = 2048
#define OFF_XS   (OFF_B + 14336)    // 8 warps * 64 float4 = 8192
#define OFF_LS   (OFF_B + 22528)    // ssum[8]

// ---------------------------------------------------------------------------
// PTX helpers (plain sm_103: mma.sync + ldmatrix + cp.async only)
// ---------------------------------------------------------------------------
__device__ __forceinline__ void ldsm4(uint32_t addr, uint32_t& r0, uint32_t& r1,
                                      uint32_t& r2, uint32_t& r3) {
    asm volatile("ldmatrix.sync.aligned.m8n8.x4.shared.b16 {%0,%1,%2,%3}, [%4];"
                 : "=r"(r0), "=r"(r1), "=r"(r2), "=r"(r3) : "r"(addr));
}
__device__ __forceinline__ void mma16816(float* c, const uint32_t* a,
                                         uint32_t b0, uint32_t b1) {
    asm volatile(
        "mma.sync.aligned.m16n8k16.row.col.f32.bf16.bf16.f32 "
        "{%0,%1,%2,%3}, {%4,%5,%6,%7}, {%8,%9}, {%0,%1,%2,%3};"
        : "+f"(c[0]), "+f"(c[1]), "+f"(c[2]), "+f"(c[3])
        : "r"(a[0]), "r"(a[1]), "r"(a[2]), "r"(a[3]), "r"(b0), "r"(b1));
}
__device__ __forceinline__ void cpasync16(uint32_t dst, const void* src) {
    asm volatile("cp.async.cg.shared.global [%0], [%1], 16;" :: "r"(dst), "l"(src));
}
__device__ __forceinline__ void cpcommit() { asm volatile("cp.async.commit_group;"); }
__device__ __forceinline__ void cpwait1()  { asm volatile("cp.async.wait_group 1;"); }

// pack score (s = bn+2 - 2*dot, guaranteed in (1,4)) + 10-bit index into a
// monotonic u32: ordering == (score asc, index asc)  -> tie-break for free.
__device__ __forceinline__ uint32_t packsk(float s, int k) {
    uint32_t b = (uint32_t)__float_as_int(s) - 0x3F800000u;
    return ((b >> 2) << 10) | (uint32_t)k;
}
__device__ __forceinline__ void ins3u(uint32_t p,
                                      uint32_t& v0, uint32_t& v1, uint32_t& v2) {
    if (p < v2) {
        if (p < v0)      { v2 = v1; v1 = v0; v0 = p; }
        else if (p < v1) { v2 = v1; v1 = p; }
        else             { v2 = p; }
    }
}

// ---------------------------------------------------------------------------
// prep: codebook -> bf16, code norms raw + biased, reset loss counter
// ---------------------------------------------------------------------------
__global__ void prep_cb_kernel(const float* __restrict__ cb,
                               __nv_bfloat16* __restrict__ cbb,
                               float* __restrict__ cbn,
                               float* __restrict__ cbnb, int* __restrict__ ctr)
{
    if (blockIdx.x == 0 && threadIdx.x == 0) *ctr = 0;
    int gw   = (blockIdx.x * blockDim.x + threadIdx.x) >> 5;
    int lane = threadIdx.x & 31;
    if (gw >= 1024) return;
    const float4* p = (const float4*)(cb + (size_t)gw * D_DIM);
    float4 v0 = p[lane * 2], v1 = p[lane * 2 + 1];
    float s = v0.x*v0.x + v0.y*v0.y + v0.z*v0.z + v0.w*v0.w
            + v1.x*v1.x + v1.y*v1.y + v1.z*v1.z + v1.w*v1.w;
#pragma unroll
    for (int o = 16; o > 0; o >>= 1) s += __shfl_xor_sync(0xffffffffu, s, o);
    if (lane == 0) { cbn[gw] = s; cbnb[gw] = s + 2.0f; }
    __nv_bfloat162 b0 = __floats2bfloat162_rn(v0.x, v0.y);
    __nv_bfloat162 b1 = __floats2bfloat162_rn(v0.z, v0.w);
    __nv_bfloat162 b2 = __floats2bfloat162_rn(v1.x, v1.y);
    __nv_bfloat162 b3 = __floats2bfloat162_rn(v1.z, v1.w);
    uint4 u;
    u.x = *(uint32_t*)&b0; u.y = *(uint32_t*)&b1;
    u.z = *(uint32_t*)&b2; u.w = *(uint32_t*)&b3;
    *(uint4*)(cbb + (size_t)gw * D_DIM + lane * 8) = u;
}

// ---------------------------------------------------------------------------
// fused kernel: bf16 mma.sync coarse top-4 (packed-u32 scores) + exact fp32
// refine + gather + loss — one launch.
// ---------------------------------------------------------------------------
__global__ void __launch_bounds__(256, 2)
vq_fused_kernel(const float* __restrict__ x, const __nv_bfloat16* __restrict__ cbb,
                const float* __restrict__ cbn, const float* __restrict__ cbnb,
                const float* __restrict__ cb,
                float* __restrict__ outq, float* __restrict__ outidx,
                float* __restrict__ partial, float* __restrict__ lossOut,
                int* __restrict__ ctr, float inv)
{
    extern __shared__ char sm[];
    const uint32_t smb = (uint32_t)__cvta_generic_to_shared(sm);

    const int tid  = threadIdx.x;
    const int lane = tid & 31, wid = tid >> 5;
    const int gid  = lane >> 2, tig = lane & 3;
    const int wm   = wid & 3, wn = wid >> 2;
    const int rm   = wm * 32;          // warp row base within block tile
    const int cnW  = wn * 64;          // warp col base within 128-code chunk
    const int rowBase = blockIdx.x * 128;

    const int lc = tid >> 1, lh = tid & 1;   // B loads: code row, half

    // stage x tile: 128 rows x 256 d, fp32 -> bf16, swizzled 16B units
    {
        int r = tid >> 1, h = tid & 1;
        const float4* xp = (const float4*)(x + (size_t)(rowBase + r) * D_DIM + h * 128);
#pragma unroll
        for (int j = 0; j < 16; ++j) {
            float4 v0 = xp[2 * j], v1 = xp[2 * j + 1];
            __nv_bfloat162 p0 = __floats2bfloat162_rn(v0.x, v0.y);
            __nv_bfloat162 p1 = __floats2bfloat162_rn(v0.z, v0.w);
            __nv_bfloat162 p2 = __floats2bfloat162_rn(v1.x, v1.y);
            __nv_bfloat162 p3 = __floats2bfloat162_rn(v1.z, v1.w);
            uint4 u;
            u.x = *(uint32_t*)&p0; u.y = *(uint32_t*)&p1;
            u.z = *(uint32_t*)&p2; u.w = *(uint32_t*)&p3;
            int ui = h * 16 + j;
            *(uint4*)(sm + r * 512 + ((ui ^ (r & 7)) << 4)) = u;
        }
    }

    // B ring loader for stage t (buf = t % 3), 64-d slice of a 128-code chunk
    auto stage_load = [&](int t) {
        const __nv_bfloat16* src =
            cbb + (size_t)((t >> 2) * 128 + lc) * D_DIM + (t & 3) * 64;
        uint32_t dst = smb + OFF_B + (uint32_t)(t % 3) * 16384u + lc * 128;
#pragma unroll
        for (int j = 0; j < 4; ++j) {
            int u = lh * 4 + j;
            cpasync16(dst + ((u ^ (lc & 7)) << 4), src + u * 8);
        }
    };

    stage_load(0); cpcommit();
    stage_load(1); cpcommit();

    // candidate state: 4 row-slots x top-3 packed (score|k) u32
    uint32_t cu[4][3];
#pragma unroll
    for (int i = 0; i < 4; ++i)
#pragma unroll
        for (int t = 0; t < 3; ++t) cu[i][t] = U32_BIG;

    float acc[2][8][4];
    const int m = lane >> 3, rr = lane & 7;

    for (int s = 0; s < 32; ++s) {
        cpwait1();            // group s complete (pending <= group s+1)
        __syncthreads();      // all warps: buffer s visible, stage s-1 compute done
        if (s + 2 < 32) stage_load(s + 2);   // buf (s+2)%3 == (s-1)%3: free now
        cpcommit();

        const int chunk = s >> 2, ds = s & 3;
        const uint32_t bufb = smb + OFF_B + (uint32_t)(s % 3) * 16384u;

        if (ds == 0) {
#pragma unroll
            for (int mi = 0; mi < 2; ++mi)
#pragma unroll
                for (int nj = 0; nj < 8; ++nj)
#pragma unroll
                    for (int q = 0; q < 4; ++q) acc[mi][nj][q] = 0.f;
        }

#pragma unroll
        for (int ks = 0; ks < 4; ++ks) {
            uint32_t a[2][4];
#pragma unroll
            for (int mi = 0; mi < 2; ++mi) {
                int row = rm + mi * 16 + (m & 1) * 8 + rr;
                int u = ds * 8 + ks * 2 + (m >> 1);
                ldsm4(smb + row * 512 + ((u ^ (row & 7)) << 4),
                      a[mi][0], a[mi][1], a[mi][2], a[mi][3]);
            }
#pragma unroll
            for (int nh = 0; nh < 2; ++nh) {
                uint32_t b[2][4];
#pragma unroll
                for (int g = 0; g < 2; ++g) {
                    int cr = cnW + nh * 32 + g * 16 + (m & 1) * 8 + rr;
                    int u = ks * 2 + (m >> 1);
                    ldsm4(bufb + cr * 128 + ((u ^ (cr & 7)) << 4),
                          b[g][0], b[g][1], b[g][2], b[g][3]);
                }
#pragma unroll
                for (int mi = 0; mi < 2; ++mi)
#pragma unroll
                    for (int g = 0; g < 2; ++g) {
                        int nj = nh * 4 + g * 2;
                        mma16816(acc[mi][nj],     a[mi], b[g][0], b[g][2]);
                        mma16816(acc[mi][nj + 1], a[mi], b[g][1], b[g][3]);
                    }
            }
        }

        if (ds == 3) {   // chunk done: fold packed scores into top-3 per row-slot
            const int kbase = chunk * 128 + cnW;
#pragma unroll
            for (int mi = 0; mi < 2; ++mi)
#pragma unroll
                for (int nj = 0; nj < 8; ++nj) {
                    int k0g = kbase + nj * 8 + 2 * tig;
                    float2 bb = __ldg((const float2*)(cbnb + k0g));  // {bn0+2, bn1+2}
                    uint32_t p00 = packsk(fmaf(-2.f, acc[mi][nj][0], bb.x), k0g);
                    uint32_t p01 = packsk(fmaf(-2.f, acc[mi][nj][1], bb.y), k0g + 1);
                    uint32_t p10 = packsk(fmaf(-2.f, acc[mi][nj][2], bb.x), k0g);
                    uint32_t p11 = packsk(fmaf(-2.f, acc[mi][nj][3], bb.y), k0g + 1);
                    int r0 = mi * 2, r1 = mi * 2 + 1;
                    ins3u(p00, cu[r0][0], cu[r0][1], cu[r0][2]);
                    ins3u(p01, cu[r0][0], cu[r0][1], cu[r0][2]);
                    ins3u(p10, cu[r1][0], cu[r1][1], cu[r1][2]);
                    ins3u(p11, cu[r1][0], cu[r1][1], cu[r1][2]);
                }
        }
    }

    // ---- merge: 8 owners x top-3 packed -> top-4 per row, kept in SMEM ----
    __syncthreads();
    uint32_t* MU = (uint32_t*)(sm + OFF_MU);
    int* candS = (int*)(sm + OFF_CSR);
    const int owner = wn * 4 + tig;
#pragma unroll
    for (int ri = 0; ri < 4; ++ri) {
        int rloc = rm + (ri >> 1) * 16 + (ri & 1) * 8 + gid;
#pragma unroll
        for (int t = 0; t < 3; ++t)
            MU[rloc * 24 + owner * 3 + t] = cu[ri][t];
    }
    __syncthreads();
    if (tid < 128) {
        uint32_t* mu = MU + tid * 24;
#pragma unroll 1
        for (int t = 0; t < NCAND; ++t) {
            uint32_t bv = mu[0]; int bp = 0;
            for (int j = 1; j < 24; ++j) {
                uint32_t v = mu[j];
                if (v < bv) { bv = v; bp = j; }
            }
            mu[bp] = U32_BIG;
            candS[tid * NCAND + t] = (int)(bv & 1023u);
        }
    }
    __syncthreads();

    // ---- refine + gather + loss: 8 warps x 16 rows (exact fp32) ----
    float4* xs = (float4*)(sm + OFF_XS) + wid * 64;   // per-warp 1KB x-row stage
    float* ssumL = (float*)(sm + OFF_LS);
    float wl = 0.f;

#pragma unroll 1
    for (int i = 0; i < 16; ++i) {
        int r = wid * 16 + i;
        int row = rowBase + r;

        const float4* xp = (const float4*)(x + (size_t)row * D_DIM);
        float4 v0 = xp[lane * 2], v1 = xp[lane * 2 + 1];
        xs[lane * 2] = v0;
        xs[lane * 2 + 1] = v1;
        float an = v0.x*v0.x + v0.y*v0.y + v0.z*v0.z + v0.w*v0.w
                 + v1.x*v1.x + v1.y*v1.y + v1.z*v1.z + v1.w*v1.w;
#pragma unroll
        for (int o = 16; o > 0; o >>= 1) an += __shfl_xor_sync(0xffffffffu, an, o);
        __syncwarp();

        int ci = lane >> 3, q = lane & 7;
        int k = candS[r * NCAND + ci];
        const float4* ep = (const float4*)(cb + (size_t)k * D_DIM);
        float acc2 = 0.f;
#pragma unroll
        for (int j = 0; j < 8; ++j) {
            float4 e  = ep[q + 8 * j];
            float4 xv = xs[q + 8 * j];
            acc2 = fmaf(xv.x, e.x, acc2);
            acc2 = fmaf(xv.y, e.y, acc2);
            acc2 = fmaf(xv.z, e.z, acc2);
            acc2 = fmaf(xv.w, e.w, acc2);
        }
        acc2 += __shfl_xor_sync(0xffffffffu, acc2, 1);
        acc2 += __shfl_xor_sync(0xffffffffu, acc2, 2);
        acc2 += __shfl_xor_sync(0xffffffffu, acc2, 4);

        float t = an + cbn[k];
        float dist = t - 2.0f * acc2;
#pragma unroll
        for (int o = 8; o <= 16; o <<= 1) {
            float d2 = __shfl_xor_sync(0xffffffffu, dist, o);
            int   k2 = __shfl_xor_sync(0xffffffffu, k, o);
            if (d2 < dist || (d2 == dist && k2 < k)) { dist = d2; k = k2; }
        }

        // gather + loss with the winning code
        const float4* cp = (const float4*)(cb + (size_t)k * D_DIM);
        float4* op = (float4*)(outq + (size_t)row * D_DIM);
        float4 q0 = cp[lane * 2], q1 = cp[lane * 2 + 1];
        op[lane * 2] = q0;
        op[lane * 2 + 1] = q1;
        float dx0 = q0.x - v0.x, dy0 = q0.y - v0.y, dz0 = q0.z - v0.z, dw0 = q0.w - v0.w;
        float dx1 = q1.x - v1.x, dy1 = q1.y - v1.y, dz1 = q1.z - v1.z, dw1 = q1.w - v1.w;
        float s = dx0*dx0 + dy0*dy0 + dz0*dz0 + dw0*dw0
                + dx1*dx1 + dy1*dy1 + dz1*dz1 + dw1*dw1;
#pragma unroll
        for (int o = 16; o > 0; o >>= 1) s += __shfl_xor_sync(0xffffffffu, s, o);
        if (lane == 0) {
            wl += s;
            if (outidx) outidx[row] = (float)k;
        }
        __syncwarp();
    }

    if (lane == 0) ssumL[wid] = wl;
    __syncthreads();
    __shared__ int sflag;
    if (tid == 0) {
        float tt = 0.f;
        for (int i = 0; i < 8; ++i) tt += ssumL[i];
        partial[blockIdx.x] = tt;
        __threadfence();
        int old = atomicAdd(ctr, 1);
        sflag = (old == (int)gridDim.x - 1);
    }
    __syncthreads();
    if (sflag) {
        // fixed-order deterministic reduction of all partials by the last CTA
        int nb = gridDim.x;
        float a2 = 0.f;
        for (int i = tid; i < nb; i += 256) a2 += __ldcg(partial + i);
#pragma unroll
        for (int o = 16; o > 0; o >>= 1) a2 += __shfl_xor_sync(0xffffffffu, a2, o);
        if (lane == 0) ssumL[wid] = a2;
        __syncthreads();
        if (tid == 0 && lossOut) {
            float tt = 0.f;
            for (int i = 0; i < 8; ++i) tt += ssumL[i];
            *lossOut = tt * inv;
        }
    }
}

// ---------------------------------------------------------------------------
extern "C" void kernel_launch(void* const* d_in, const int* in_sizes, int n_in,
                              void* d_out, int out_size)
{
    const float* x  = (const float*)d_in[0];
    const float* cb = (const float*)d_in[1];
    int N = in_sizes[0] / D_DIM;   // 32768

    float* out  = (float*)d_out;
    float* outq = out;
    long long qn  = (long long)N * D_DIM;
    long long rem = (long long)out_size - qn;
    float* outidx  = nullptr;
    float* outloss = nullptr;
    if (rem >= (long long)N) {
        outidx = out + qn;
        if (rem >= (long long)N + 1) outloss = out + qn + N;
    } else if (rem >= 1) {
        outloss = out + qn;
    }

    __nv_bfloat16* cbb; float *cbn, *cbnb, *part; int *ctr;
    cudaGetSymbolAddress((void**)&cbb,  g_cbb);
    cudaGetSymbolAddress((void**)&cbn,  g_codenorm);
    cudaGetSymbolAddress((void**)&cbnb, g_codenormb);
    cudaGetSymbolAddress((void**)&part, g_partial);
    cudaGetSymbolAddress((void**)&ctr,  g_ctr);

    prep_cb_kernel<<<128, 256>>>(cb, cbb, cbn, cbnb, ctr);

    cudaFuncSetAttribute(vq_fused_kernel,
                         cudaFuncAttributeMaxDynamicSharedMemorySize, CO_SMEM);
    vq_fused_kernel<<<N / 128, 256, CO_SMEM>>>(x, cbb, cbn, cbnb, cb, outq,
                                               outidx, part, outloss, ctr,
                                               1.0f / (float)((long long)N * D_DIM));
}

// round 17
// speedup vs baseline: 1.8378x; 1.0693x over previous
#include <cuda_runtime.h>
#include <cuda_bf16.h>
#include <cstdint>

#define D_DIM 256
#define NCAND 4
#define U32_BIG 0xFFFFFFFFu

// scratch (static device globals; no allocations)
__device__ __nv_bfloat16 g_cbb[1024 * 256];
__device__ float g_codenorm[1024];     // raw ||e||^2 (refine)
__device__ float g_codenormb[1024];    // ||e||^2 + 2.0f (coarse, packed-score bias)
__device__ float g_partial[512];
__device__ int   g_ctr;

// smem layout: A tile 64KB | B ring 3x16KB (reused by merge/refine tail)
#define OFF_B   65536
#define CO_SMEM (65536 + 49152)   // 114688 -> 2 CTAs/SM

// tail-phase smem offsets (inside the B-ring region, dead after main loop)
#define OFF_MU   OFF_B              // 128*16 u32 = 8192
#define OFF_CSR  (OFF_B + 8192)     // candS 128*4 ints = 2048
#define OFF_XS   (OFF_B + 10240)    // 8 warps * 64 float4 = 8192
#define OFF_LS   (OFF_B + 18432)    // ssum[8]

// ---------------------------------------------------------------------------
// PTX helpers (plain sm_103: mma.sync + ldmatrix + cp.async only)
// ---------------------------------------------------------------------------
__device__ __forceinline__ void ldsm4(uint32_t addr, uint32_t& r0, uint32_t& r1,
                                      uint32_t& r2, uint32_t& r3) {
    asm volatile("ldmatrix.sync.aligned.m8n8.x4.shared.b16 {%0,%1,%2,%3}, [%4];"
                 : "=r"(r0), "=r"(r1), "=r"(r2), "=r"(r3) : "r"(addr));
}
__device__ __forceinline__ void mma16816(float* c, const uint32_t* a,
                                         uint32_t b0, uint32_t b1) {
    asm volatile(
        "mma.sync.aligned.m16n8k16.row.col.f32.bf16.bf16.f32 "
        "{%0,%1,%2,%3}, {%4,%5,%6,%7}, {%8,%9}, {%0,%1,%2,%3};"
        : "+f"(c[0]), "+f"(c[1]), "+f"(c[2]), "+f"(c[3])
        : "r"(a[0]), "r"(a[1]), "r"(a[2]), "r"(a[3]), "r"(b0), "r"(b1));
}
__device__ __forceinline__ void cpasync16(uint32_t dst, const void* src) {
    asm volatile("cp.async.cg.shared.global [%0], [%1], 16;" :: "r"(dst), "l"(src));
}
__device__ __forceinline__ void cpcommit() { asm volatile("cp.async.commit_group;"); }
__device__ __forceinline__ void cpwait1()  { asm volatile("cp.async.wait_group 1;"); }

// pack score (s = bn+2 - 2*dot, guaranteed in (1,4)) + 10-bit index into a
// monotonic u32: ordering == (score asc, index asc)  -> tie-break for free.
__device__ __forceinline__ uint32_t packsk(float s, int k) {
    uint32_t b = (uint32_t)__float_as_int(s) - 0x3F800000u;
    return ((b >> 2) << 10) | (uint32_t)k;
}
__device__ __forceinline__ void ins2u(uint32_t p, uint32_t& v0, uint32_t& v1) {
    if (p < v1) {
        if (p < v0) { v1 = v0; v0 = p; }
        else        { v1 = p; }
    }
}

// ---------------------------------------------------------------------------
// prep: codebook -> bf16, code norms raw + biased, reset loss counter
// ---------------------------------------------------------------------------
__global__ void prep_cb_kernel(const float* __restrict__ cb,
                               __nv_bfloat16* __restrict__ cbb,
                               float* __restrict__ cbn,
                               float* __restrict__ cbnb, int* __restrict__ ctr)
{
    if (blockIdx.x == 0 && threadIdx.x == 0) *ctr = 0;
    int gw   = (blockIdx.x * blockDim.x + threadIdx.x) >> 5;
    int lane = threadIdx.x & 31;
    if (gw >= 1024) return;
    const float4* p = (const float4*)(cb + (size_t)gw * D_DIM);
    float4 v0 = p[lane * 2], v1 = p[lane * 2 + 1];
    float s = v0.x*v0.x + v0.y*v0.y + v0.z*v0.z + v0.w*v0.w
            + v1.x*v1.x + v1.y*v1.y + v1.z*v1.z + v1.w*v1.w;
#pragma unroll
    for (int o = 16; o > 0; o >>= 1) s += __shfl_xor_sync(0xffffffffu, s, o);
    if (lane == 0) { cbn[gw] = s; cbnb[gw] = s + 2.0f; }
    __nv_bfloat162 b0 = __floats2bfloat162_rn(v0.x, v0.y);
    __nv_bfloat162 b1 = __floats2bfloat162_rn(v0.z, v0.w);
    __nv_bfloat162 b2 = __floats2bfloat162_rn(v1.x, v1.y);
    __nv_bfloat162 b3 = __floats2bfloat162_rn(v1.z, v1.w);
    uint4 u;
    u.x = *(uint32_t*)&b0; u.y = *(uint32_t*)&b1;
    u.z = *(uint32_t*)&b2; u.w = *(uint32_t*)&b3;
    *(uint4*)(cbb + (size_t)gw * D_DIM + lane * 8) = u;
}

// ---------------------------------------------------------------------------
// fused kernel: bf16 mma.sync coarse top-4 (packed-u32 scores) + exact fp32
// refine + gather + loss — one launch.
// Non-uniform row tiles for SM load balance (placement LUT[bid % NSM]):
//   bids [0,152): 128 rows   bids [152,264): 96 rows   bids [264,304): 64 rows
// ---------------------------------------------------------------------------
__global__ void __launch_bounds__(256, 2)
vq_fused_kernel(const float* __restrict__ x, const __nv_bfloat16* __restrict__ cbb,
                const float* __restrict__ cbn, const float* __restrict__ cbnb,
                const float* __restrict__ cb,
                float* __restrict__ outq, float* __restrict__ outidx,
                float* __restrict__ partial, float* __restrict__ lossOut,
                int* __restrict__ ctr, float inv)
{
    extern __shared__ char sm[];
    const uint32_t smb = (uint32_t)__cvta_generic_to_shared(sm);

    const int tid  = threadIdx.x;
    const int lane = tid & 31, wid = tid >> 5;
    const int gid  = lane >> 2, tig = lane & 3;
    const int wm   = wid & 3, wn = wid >> 2;
    const int rm   = wm * 32;          // warp row base within block tile
    const int cnW  = wn * 64;          // warp col base within 128-code chunk
    const int bid  = blockIdx.x;

    int rows, rowBase;
    if (bid < 152)      { rows = 128; rowBase = bid * 128; }
    else if (bid < 264) { rows = 96;  rowBase = 19456 + (bid - 152) * 96; }
    else                { rows = 64;  rowBase = 30208 + (bid - 264) * 64; }
    const bool active = (rm < rows);   // warp has compute rows

    const int lc = tid >> 1, lh = tid & 1;   // B loads: code row, half

    // stage x tile: rows x 256 d, fp32 -> bf16, swizzled 16B units
    {
        int r = tid >> 1, h = tid & 1;
        if (r < rows) {
            const float4* xp = (const float4*)(x + (size_t)(rowBase + r) * D_DIM + h * 128);
#pragma unroll
            for (int j = 0; j < 16; ++j) {
                float4 v0 = xp[2 * j], v1 = xp[2 * j + 1];
                __nv_bfloat162 p0 = __floats2bfloat162_rn(v0.x, v0.y);
                __nv_bfloat162 p1 = __floats2bfloat162_rn(v0.z, v0.w);
                __nv_bfloat162 p2 = __floats2bfloat162_rn(v1.x, v1.y);
                __nv_bfloat162 p3 = __floats2bfloat162_rn(v1.z, v1.w);
                uint4 u;
                u.x = *(uint32_t*)&p0; u.y = *(uint32_t*)&p1;
                u.z = *(uint32_t*)&p2; u.w = *(uint32_t*)&p3;
                int ui = h * 16 + j;
                *(uint4*)(sm + r * 512 + ((ui ^ (r & 7)) << 4)) = u;
            }
        }
    }

    // B ring loader for stage t (buf = t % 3), 64-d slice of a 128-code chunk
    auto stage_load = [&](int t) {
        const __nv_bfloat16* src =
            cbb + (size_t)((t >> 2) * 128 + lc) * D_DIM + (t & 3) * 64;
        uint32_t dst = smb + OFF_B + (uint32_t)(t % 3) * 16384u + lc * 128;
#pragma unroll
        for (int j = 0; j < 4; ++j) {
            int u = lh * 4 + j;
            cpasync16(dst + ((u ^ (lc & 7)) << 4), src + u * 8);
        }
    };

    stage_load(0); cpcommit();
    stage_load(1); cpcommit();

    // candidate state: 4 row-slots x top-2 packed (score|k) u32
    uint32_t cu[4][2];
#pragma unroll
    for (int i = 0; i < 4; ++i) { cu[i][0] = U32_BIG; cu[i][1] = U32_BIG; }

    float acc[2][8][4];
    const int m = lane >> 3, rr = lane & 7;

    for (int s = 0; s < 32; ++s) {
        cpwait1();            // group s complete (pending <= group s+1)
        __syncthreads();      // all warps: buffer s visible, stage s-1 compute done
        if (s + 2 < 32) stage_load(s + 2);   // buf (s+2)%3 == (s-1)%3: free now
        cpcommit();

        if (active) {
            const int chunk = s >> 2, ds = s & 3;
            const uint32_t bufb = smb + OFF_B + (uint32_t)(s % 3) * 16384u;

            if (ds == 0) {
#pragma unroll
                for (int mi = 0; mi < 2; ++mi)
#pragma unroll
                    for (int nj = 0; nj < 8; ++nj)
#pragma unroll
                        for (int q = 0; q < 4; ++q) acc[mi][nj][q] = 0.f;
            }

#pragma unroll
            for (int ks = 0; ks < 4; ++ks) {
                uint32_t a[2][4];
#pragma unroll
                for (int mi = 0; mi < 2; ++mi) {
                    int row = rm + mi * 16 + (m & 1) * 8 + rr;
                    int u = ds * 8 + ks * 2 + (m >> 1);
                    ldsm4(smb + row * 512 + ((u ^ (row & 7)) << 4),
                          a[mi][0], a[mi][1], a[mi][2], a[mi][3]);
                }
#pragma unroll
                for (int nh = 0; nh < 2; ++nh) {
                    uint32_t b[2][4];
#pragma unroll
                    for (int g = 0; g < 2; ++g) {
                        int cr = cnW + nh * 32 + g * 16 + (m & 1) * 8 + rr;
                        int u = ks * 2 + (m >> 1);
                        ldsm4(bufb + cr * 128 + ((u ^ (cr & 7)) << 4),
                              b[g][0], b[g][1], b[g][2], b[g][3]);
                    }
#pragma unroll
                    for (int mi = 0; mi < 2; ++mi)
#pragma unroll
                        for (int g = 0; g < 2; ++g) {
                            int nj = nh * 4 + g * 2;
                            mma16816(acc[mi][nj],     a[mi], b[g][0], b[g][2]);
                            mma16816(acc[mi][nj + 1], a[mi], b[g][1], b[g][3]);
                        }
                }
            }

            if (ds == 3) {   // chunk done: fold packed scores into top-2 per slot
                const int kbase = chunk * 128 + cnW;
#pragma unroll
                for (int mi = 0; mi < 2; ++mi)
#pragma unroll
                    for (int nj = 0; nj < 8; ++nj) {
                        int k0g = kbase + nj * 8 + 2 * tig;
                        float2 bb = __ldg((const float2*)(cbnb + k0g));
                        uint32_t p00 = packsk(fmaf(-2.f, acc[mi][nj][0], bb.x), k0g);
                        uint32_t p01 = packsk(fmaf(-2.f, acc[mi][nj][1], bb.y), k0g + 1);
                        uint32_t p10 = packsk(fmaf(-2.f, acc[mi][nj][2], bb.x), k0g);
                        uint32_t p11 = packsk(fmaf(-2.f, acc[mi][nj][3], bb.y), k0g + 1);
                        int r0 = mi * 2, r1 = mi * 2 + 1;
                        ins2u(p00, cu[r0][0], cu[r0][1]);
                        ins2u(p01, cu[r0][0], cu[r0][1]);
                        ins2u(p10, cu[r1][0], cu[r1][1]);
                        ins2u(p11, cu[r1][0], cu[r1][1]);
                    }
            }
        }
    }

    // ---- merge: 8 owners x top-2 packed -> top-4 per row, kept in SMEM ----
    __syncthreads();
    uint32_t* MU = (uint32_t*)(sm + OFF_MU);
    int* candS = (int*)(sm + OFF_CSR);
    const int owner = wn * 4 + tig;
    if (active) {
#pragma unroll
        for (int ri = 0; ri < 4; ++ri) {
            int rloc = rm + (ri >> 1) * 16 + (ri & 1) * 8 + gid;
            MU[rloc * 16 + owner * 2 + 0] = cu[ri][0];
            MU[rloc * 16 + owner * 2 + 1] = cu[ri][1];
        }
    }
    __syncthreads();
    if (tid < rows) {
        uint32_t* mu = MU + tid * 16;
#pragma unroll 1
        for (int t = 0; t < NCAND; ++t) {
            uint32_t bv = mu[0]; int bp = 0;
            for (int j = 1; j < 16; ++j) {
                uint32_t v = mu[j];
                if (v < bv) { bv = v; bp = j; }
            }
            mu[bp] = U32_BIG;
            candS[tid * NCAND + t] = (int)(bv & 1023u);
        }
    }
    __syncthreads();

    // ---- refine + gather + loss: 8 warps x rows/8 rows (exact fp32) ----
    float4* xs = (float4*)(sm + OFF_XS) + wid * 64;   // per-warp 1KB x-row stage
    float* ssumL = (float*)(sm + OFF_LS);
    float wl = 0.f;
    const int rPerWarp = rows >> 3;

#pragma unroll 1
    for (int i = 0; i < rPerWarp; ++i) {
        int r = wid * rPerWarp + i;
        int row = rowBase + r;

        const float4* xp = (const float4*)(x + (size_t)row * D_DIM);
        float4 v0 = xp[lane * 2], v1 = xp[lane * 2 + 1];
        xs[lane * 2] = v0;
        xs[lane * 2 + 1] = v1;
        float an = v0.x*v0.x + v0.y*v0.y + v0.z*v0.z + v0.w*v0.w
                 + v1.x*v1.x + v1.y*v1.y + v1.z*v1.z + v1.w*v1.w;
#pragma unroll
        for (int o = 16; o > 0; o >>= 1) an += __shfl_xor_sync(0xffffffffu, an, o);
        __syncwarp();

        int ci = lane >> 3, q = lane & 7;
        int k = candS[r * NCAND + ci];
        const float4* ep = (const float4*)(cb + (size_t)k * D_DIM);
        float acc2 = 0.f;
#pragma unroll
        for (int j = 0; j < 8; ++j) {
            float4 e  = ep[q + 8 * j];
            float4 xv = xs[q + 8 * j];
            acc2 = fmaf(xv.x, e.x, acc2);
            acc2 = fmaf(xv.y, e.y, acc2);
            acc2 = fmaf(xv.z, e.z, acc2);
            acc2 = fmaf(xv.w, e.w, acc2);
        }
        acc2 += __shfl_xor_sync(0xffffffffu, acc2, 1);
        acc2 += __shfl_xor_sync(0xffffffffu, acc2, 2);
        acc2 += __shfl_xor_sync(0xffffffffu, acc2, 4);

        float t = an + cbn[k];
        float dist = t - 2.0f * acc2;
#pragma unroll
        for (int o = 8; o <= 16; o <<= 1) {
            float d2 = __shfl_xor_sync(0xffffffffu, dist, o);
            int   k2 = __shfl_xor_sync(0xffffffffu, k, o);
            if (d2 < dist || (d2 == dist && k2 < k)) { dist = d2; k = k2; }
        }

        // gather + loss with the winning code
        const float4* cp = (const float4*)(cb + (size_t)k * D_DIM);
        float4* op = (float4*)(outq + (size_t)row * D_DIM);
        float4 q0 = cp[lane * 2], q1 = cp[lane * 2 + 1];
        op[lane * 2] = q0;
        op[lane * 2 + 1] = q1;
        float dx0 = q0.x - v0.x, dy0 = q0.y - v0.y, dz0 = q0.z - v0.z, dw0 = q0.w - v0.w;
        float dx1 = q1.x - v1.x, dy1 = q1.y - v1.y, dz1 = q1.z - v1.z, dw1 = q1.w - v1.w;
        float s = dx0*dx0 + dy0*dy0 + dz0*dz0 + dw0*dw0
                + dx1*dx1 + dy1*dy1 + dz1*dz1 + dw1*dw1;
#pragma unroll
        for (int o = 16; o > 0; o >>= 1) s += __shfl_xor_sync(0xffffffffu, s, o);
        if (lane == 0) {
            wl += s;
            if (outidx) outidx[row] = (float)k;
        }
        __syncwarp();
    }

    if (lane == 0) ssumL[wid] = wl;
    __syncthreads();
    __shared__ int sflag;
    if (tid == 0) {
        float tt = 0.f;
        for (int i = 0; i < 8; ++i) tt += ssumL[i];
        partial[bid] = tt;
        __threadfence();
        int old = atomicAdd(ctr, 1);
        sflag = (old == (int)gridDim.x - 1);
    }
    __syncthreads();
    if (sflag) {
        // fixed-order deterministic reduction of all partials by the last CTA
        int nb = gridDim.x;
        float a2 = 0.f;
        for (int i = tid; i < nb; i += 256) a2 += __ldcg(partial + i);
#pragma unroll
        for (int o = 16; o > 0; o >>= 1) a2 += __shfl_xor_sync(0xffffffffu, a2, o);
        if (lane == 0) ssumL[wid] = a2;
        __syncthreads();
        if (tid == 0 && lossOut) {
            float tt = 0.f;
            for (int i = 0; i < 8; ++i) tt += ssumL[i];
            *lossOut = tt * inv;
        }
    }
}

// ---------------------------------------------------------------------------
extern "C" void kernel_launch(void* const* d_in, const int* in_sizes, int n_in,
                              void* d_out, int out_size)
{
    const float* x  = (const float*)d_in[0];
    const float* cb = (const float*)d_in[1];
    int N = in_sizes[0] / D_DIM;   // 32768

    float* out  = (float*)d_out;
    float* outq = out;
    long long qn  = (long long)N * D_DIM;
    long long rem = (long long)out_size - qn;
    float* outidx  = nullptr;
    float* outloss = nullptr;
    if (rem >= (long long)N) {
        outidx = out + qn;
        if (rem >= (long long)N + 1) outloss = out + qn + N;
    } else if (rem >= 1) {
        outloss = out + qn;
    }

    __nv_bfloat16* cbb; float *cbn, *cbnb, *part; int *ctr;
    cudaGetSymbolAddress((void**)&cbb,  g_cbb);
    cudaGetSymbolAddress((void**)&cbn,  g_codenorm);
    cudaGetSymbolAddress((void**)&cbnb, g_codenormb);
    cudaGetSymbolAddress((void**)&part, g_partial);
    cudaGetSymbolAddress((void**)&ctr,  g_ctr);

    prep_cb_kernel<<<128, 256>>>(cb, cbb, cbn, cbnb, ctr);

    cudaFuncSetAttribute(vq_fused_kernel,
                         cudaFuncAttributeMaxDynamicSharedMemorySize, CO_SMEM);
    // 304 CTAs: 152x128-row + 112x96-row + 40x64-row = 32768 rows
    vq_fused_kernel<<<304, 256, CO_SMEM>>>(x, cbb, cbn, cbnb, cb, outq,
                                           outidx, part, outloss, ctr,
                                           1.0f / (float)((long long)N * D_DIM));
}